// round 6
// baseline (speedup 1.0000x reference)
#include <cuda_runtime.h>

// GyroLoss forward, single fused kernel — quaternion formulation, one thread
// per 16-increment group. Two independent 8-subtrees (ILP), intrinsic math,
// custom polynomial atan2. Level-5 via lane-pair shuffle. Last-block finalize.

#define DT_F 0.01f
#define HUBER_F 0.005f
#define NPER4 2048
#define NPER5 1024
#define N0 5
#define TPB 128

__device__ double g_sum4 = 0.0;
__device__ double g_sum5 = 0.0;
__device__ unsigned int g_count = 0u;

// Hamilton product c = a ⊗ b  (R(a⊗b) = R(a)·R(b)); w at index 0.
__device__ __forceinline__ void qmul(const float a[4], const float b[4], float c[4]) {
    c[0] = a[0]*b[0] - a[1]*b[1] - a[2]*b[2] - a[3]*b[3];
    c[1] = a[0]*b[1] + a[1]*b[0] + a[2]*b[3] - a[3]*b[2];
    c[2] = a[0]*b[2] - a[1]*b[3] + a[2]*b[0] + a[3]*b[1];
    c[3] = a[0]*b[3] + a[1]*b[2] - a[2]*b[1] + a[3]*b[0];
}

// c = conj(a) ⊗ b   (relative rotation A^T B)
__device__ __forceinline__ void qcmul(const float a[4], const float b[4], float c[4]) {
    c[0] = a[0]*b[0] + a[1]*b[1] + a[2]*b[2] + a[3]*b[3];
    c[1] = a[0]*b[1] - a[1]*b[0] - a[2]*b[3] + a[3]*b[2];
    c[2] = a[0]*b[2] + a[1]*b[3] - a[2]*b[0] - a[3]*b[1];
    c[3] = a[0]*b[3] - a[1]*b[2] + a[2]*b[1] - a[3]*b[0];
}

// exp of small phi = DT*(x,y,z) -> quaternion; (|phi|/2)^2 <= ~1e-3.
__device__ __forceinline__ void qexp_small(float x, float y, float z, float q[4]) {
    float rs = x*x + y*y + z*z;
    float hq = (0.25f * DT_F * DT_F) * rs;
    q[0] = 1.0f + hq * (-0.5f + hq * (1.0f / 24.0f));
    float sf = (0.5f * DT_F) * (1.0f + hq * (-(1.0f / 6.0f) + hq * (1.0f / 120.0f)));
    q[1] = sf * x; q[2] = sf * y; q[3] = sf * z;
}

// full-range exp (xs path): |phi| up to ~6, half-angle < ~3 -> __sinf OK
__device__ __forceinline__ void qexp_full(float x, float y, float z, float q[4]) {
    float sq = x*x + y*y + z*z;
    float a = sq * __frsqrt_rn(fmaxf(sq, 1e-16f));     // sqrt(sq), 0-safe
    float h = 0.5f * a;
    float sh = __sinf(h), ch = __cosf(h);
    float sf = __fdividef(sh, fmaxf(a, 1e-8f));
    q[0] = ch; q[1] = sf * x; q[2] = sf * y; q[3] = sf * z;
}

// minimax atan on [0,1], abs err ~1e-6
__device__ __forceinline__ float fast_atan01(float x) {
    float t = x * x;
    float p = -0.0117212f;
    p = fmaf(p, t,  0.05265332f);
    p = fmaf(p, t, -0.11643287f);
    p = fmaf(p, t,  0.19354346f);
    p = fmaf(p, t, -0.33262347f);
    p = fmaf(p, t,  0.99997726f);
    return x * p;
}

// sum of Huber(phi_i/HUBER) for phi = so3_log of quat q (branch-free).
__device__ __forceinline__ float huber3_qlog(const float q[4]) {
    float w = q[0], x = q[1], y = q[2], z = q[3];
    float sg = (w < 0.0f) ? -1.0f : 1.0f;
    w *= sg; x *= sg; y *= sg; z *= sg;
    float nv2 = x*x + y*y + z*z;
    float nv = nv2 * __frsqrt_rn(fmaxf(nv2, 1e-24f));   // sqrt, 0-safe
    // th = 2*atan2(nv, w), nv,w >= 0, branch-free
    float lo = fminf(nv, w), hi = fmaxf(nv, w);
    float at = fast_atan01(__fdividef(lo, hi));
    float th = 2.0f * ((nv <= w) ? at : (1.57079632679f - at));
    float f = __fdividef(th, fmaxf(nv, 1e-20f)) * (1.0f / HUBER_F);
    float acc = 0.0f;
#pragma unroll
    for (int t = 0; t < 3; t++) {
        float zz = f * ((t == 0) ? x : (t == 1) ? y : z);
        float az = fabsf(zz);
        acc += (az < 1.0f) ? (0.5f * zz * zz) : (az - 0.5f);
    }
    return acc;
}

// compose 8 increments (24 floats = 6 float4) into one quaternion, tree order
__device__ __forceinline__ void build8(const float4 f[6], float out[4]) {
    float v[24] = {f[0].x,f[0].y,f[0].z,f[0].w, f[1].x,f[1].y,f[1].z,f[1].w,
                   f[2].x,f[2].y,f[2].z,f[2].w, f[3].x,f[3].y,f[3].z,f[3].w,
                   f[4].x,f[4].y,f[4].z,f[4].w, f[5].x,f[5].y,f[5].z,f[5].w};
    float p0[4], p1[4], p2[4], p3[4];
    {
        float la[4], lb[4];
        qexp_small(v[0],  v[1],  v[2],  la);
        qexp_small(v[3],  v[4],  v[5],  lb);
        qmul(la, lb, p0);
        qexp_small(v[6],  v[7],  v[8],  la);
        qexp_small(v[9],  v[10], v[11], lb);
        qmul(la, lb, p1);
        qexp_small(v[12], v[13], v[14], la);
        qexp_small(v[15], v[16], v[17], lb);
        qmul(la, lb, p2);
        qexp_small(v[18], v[19], v[20], la);
        qexp_small(v[21], v[22], v[23], lb);
        qmul(la, lb, p3);
    }
    float u0[4], u1[4];
    qmul(p0, p1, u0);
    qmul(p2, p3, u1);
    qmul(u0, u1, out);
}

__global__ void __launch_bounds__(TPB)
gyro_main_kernel(const float* __restrict__ xs, const float* __restrict__ hx,
                 float* __restrict__ out, int cnt4, int cnt5) {
    int g = blockIdx.x * blockDim.x + threadIdx.x;   // group index (16 incr)

    // --- load 16 increments (48 floats = 12 float4, batched for MLP) ---
    const float4* hp = reinterpret_cast<const float4*>(hx) + (size_t)g * 12;
    float4 A[12];
#pragma unroll
    for (int k = 0; k < 12; k++) A[k] = hp[k];
    float4 xv = *reinterpret_cast<const float4*>(xs + (size_t)g * 48);

    // --- two independent 8-subtrees, then combine (ILP ~2) ---
    float qa[4], qb[4], q16[4];
    build8(&A[0], qa);
    build8(&A[6], qb);
    qmul(qa, qb, q16);

    // --- ground-truth quat for this group ---
    float qR[4];
    qexp_full(xv.x, xv.y, xv.z, qR);

    // --- level-4 residual (own group) ---
    float rel4[4];
    qcmul(q16, qR, rel4);
    float h4 = huber3_qlog(rel4);
    int i4 = g & (NPER4 - 1);
    float s4 = (i4 >= N0) ? h4 : 0.0f;

    // --- level-5: even g combines with partner g+1 (lane+1) ---
    float qp[4], rp[4];
#pragma unroll
    for (int k = 0; k < 4; k++) {
        qp[k] = __shfl_down_sync(0xFFFFFFFFu, q16[k], 1);
        rp[k] = __shfl_down_sync(0xFFFFFFFFu, qR[k], 1);
    }
    float q32[4], r32[4], rel5[4];
    qmul(q16, qp, q32);
    qmul(qR, rp, r32);
    qcmul(q32, r32, rel5);
    float h5 = huber3_qlog(rel5);
    float s5 = 0.0f;
    if ((g & 1) == 0) {
        int j5 = (g >> 1) & (NPER5 - 1);
        if (j5 >= N0) s5 = h5;
    }

    // --- reduction ---
#pragma unroll
    for (int off = 16; off > 0; off >>= 1) {
        s4 += __shfl_down_sync(0xFFFFFFFFu, s4, off);
        s5 += __shfl_down_sync(0xFFFFFFFFu, s5, off);
    }
    __shared__ float sh4[TPB / 32];
    __shared__ float sh5[TPB / 32];
    int lane = threadIdx.x & 31;
    int warp = threadIdx.x >> 5;
    if (lane == 0) { sh4[warp] = s4; sh5[warp] = s5; }
    __syncthreads();

    if (threadIdx.x == 0) {
        float b4 = 0.0f, b5 = 0.0f;
#pragma unroll
        for (int w = 0; w < TPB / 32; w++) { b4 += sh4[w]; b5 += sh5[w]; }
        atomicAdd(&g_sum4, (double)b4);
        atomicAdd(&g_sum5, (double)b5);
        __threadfence();
        unsigned int ticket = atomicAdd(&g_count, 1u);
        if (ticket == gridDim.x - 1) {
            double s4t = atomicAdd(&g_sum4, 0.0);
            double s5t = atomicAdd(&g_sum5, 0.0);
            // loss = W*HUBER^2 * (mean4 + 0.5*mean5); W*HUBER^2 = 25
            double loss = 25.0 * (s4t / (double)cnt4 + 0.5 * s5t / (double)cnt5);
            out[0] = (float)loss;
            g_sum4 = 0.0;
            g_sum5 = 0.0;
            __threadfence();
            g_count = 0u;
        }
    }
}

extern "C" void kernel_launch(void* const* d_in, const int* in_sizes, int n_in,
                              void* d_out, int out_size) {
    const float* xs = (const float*)d_in[0];
    // d_in[1] = dp, unused by forward
    const float* hx = (const float*)d_in[2];

    int total = in_sizes[2];              // N*T*3 = 6291456
    int groups = total / 48;              // 131072 groups of 16
    int nbatch = 64;
    int g4_per_batch = groups / nbatch;   // 2048
    int g5_per_batch = g4_per_batch / 2;  // 1024
    int cnt4 = nbatch * (g4_per_batch - N0) * 3;   // 392256
    int cnt5 = nbatch * (g5_per_batch - N0) * 3;   // 195648

    gyro_main_kernel<<<groups / TPB, TPB>>>(xs, hx, (float*)d_out, cnt4, cnt5);
}